// round 3
// baseline (speedup 1.0000x reference)
#include <cuda_runtime.h>

typedef unsigned long long ull;

__device__ __forceinline__ float fast_tanh(float x) {
    float y;
    asm("tanh.approx.f32 %0, %1;" : "=f"(y) : "f"(x));
    return y;
}

__device__ __forceinline__ ull pk(float lo, float hi) {
    ull r;
    asm("mov.b64 %0, {%1, %2};" : "=l"(r) : "f"(lo), "f"(hi));
    return r;
}

__device__ __forceinline__ void upk(ull v, float& lo, float& hi) {
    asm("mov.b64 {%0, %1}, %2;" : "=f"(lo), "=f"(hi) : "l"(v));
}

// packed dual fp32 FMA (FFMA2) — only reachable via PTX fma.rn.f32x2
__device__ __forceinline__ ull fma2(ull a, ull b, ull c) {
    ull d;
    asm("fma.rn.f32x2 %0, %1, %2, %3;" : "=l"(d) : "l"(a), "l"(b), "l"(c));
    return d;
}

// Gate rows in 4H=20: i=[0,5), f=[5,10), g=[10,15), o=[15,20)
// sigmoid(z) = 0.5*tanh(z/2)+0.5 with the 1/2 folded into i/f/o weight rows.
// Gates packed as f32x2 pairs: lane pair (i_j, f_j) and (g_j, o_j).
__global__ __launch_bounds__(128) void lstm_kernel(
    const float* __restrict__ x,      // (32768, 600)
    const float* __restrict__ w_ih,   // (20, 1)
    const float* __restrict__ w_hh,   // (20, 5)
    const float* __restrict__ b_ih,   // (20,)
    const float* __restrict__ b_hh,   // (20,)
    const float* __restrict__ fc_w,   // (15, 5)
    const float* __restrict__ fc_b,   // (15,)
    const float* __restrict__ out_w,  // (1, 15)
    const float* __restrict__ out_b,  // (1,)
    float* __restrict__ out)          // (32768,)
{
    __shared__ ull s_wih_if[5], s_wih_go[5];   // packed (i_j, f_j), (g_j, o_j)
    __shared__ ull s_b_if[5],   s_b_go[5];
    __shared__ ull s_whh_if[25], s_whh_go[25]; // [j*5+k]
    __shared__ float s_fcw[75];
    __shared__ float s_fcb[15];
    __shared__ float s_outw[15];
    __shared__ float s_outb;

    const int tid = threadIdx.x;
    if (tid < 5) {
        const int j = tid;
        s_wih_if[j] = pk(w_ih[j] * 0.5f,  w_ih[5 + j] * 0.5f);
        s_wih_go[j] = pk(w_ih[10 + j],    w_ih[15 + j] * 0.5f);
        s_b_if[j] = pk((b_ih[j] + b_hh[j]) * 0.5f,
                       (b_ih[5 + j] + b_hh[5 + j]) * 0.5f);
        s_b_go[j] = pk((b_ih[10 + j] + b_hh[10 + j]),
                       (b_ih[15 + j] + b_hh[15 + j]) * 0.5f);
    }
    if (tid < 25) {
        const int j = tid / 5, k = tid % 5;
        s_whh_if[tid] = pk(w_hh[j * 5 + k] * 0.5f,  w_hh[(5 + j) * 5 + k] * 0.5f);
        s_whh_go[tid] = pk(w_hh[(10 + j) * 5 + k],  w_hh[(15 + j) * 5 + k] * 0.5f);
    }
    if (tid < 75) s_fcw[tid] = fc_w[tid];
    if (tid < 15) { s_fcb[tid] = fc_b[tid]; s_outw[tid] = out_w[tid]; }
    if (tid == 0) s_outb = out_b[0];
    __syncthreads();

    // Hoist all packed weights into registers (loop-invariant).
    ull wih_if[5], wih_go[5], bb_if[5], bb_go[5];
    ull whh_if[25], whh_go[25];
    #pragma unroll
    for (int j = 0; j < 5; j++) {
        wih_if[j] = s_wih_if[j]; wih_go[j] = s_wih_go[j];
        bb_if[j]  = s_b_if[j];   bb_go[j]  = s_b_go[j];
    }
    #pragma unroll
    for (int m = 0; m < 25; m++) { whh_if[m] = s_whh_if[m]; whh_go[m] = s_whh_go[m]; }

    const int seq = blockIdx.x * 128 + tid;
    const float* xr = x + (long)seq * 600;

    float h[5] = {0.f, 0.f, 0.f, 0.f, 0.f};
    float c[5] = {0.f, 0.f, 0.f, 0.f, 0.f};

    #pragma unroll 1
    for (int t0 = 0; t0 < 600; t0 += 4) {
        const float4 xv = *reinterpret_cast<const float4*>(xr + t0);
        float xs[4] = {xv.x, xv.y, xv.z, xv.w};
        #pragma unroll
        for (int u = 0; u < 4; u++) {
            const ull xx = pk(xs[u], xs[u]);
            ull hh[5];
            #pragma unroll
            for (int k = 0; k < 5; k++) hh[k] = pk(h[k], h[k]);

            #pragma unroll
            for (int j = 0; j < 5; j++) {
                ull aif = fma2(xx, wih_if[j], bb_if[j]);
                ull ago = fma2(xx, wih_go[j], bb_go[j]);
                #pragma unroll
                for (int k = 0; k < 5; k++) {
                    aif = fma2(hh[k], whh_if[j * 5 + k], aif);
                    ago = fma2(hh[k], whh_go[j * 5 + k], ago);
                }
                float zi, zf, zg, zo;
                upk(aif, zi, zf);
                upk(ago, zg, zo);
                const float iv = fmaf(fast_tanh(zi), 0.5f, 0.5f);
                const float fv = fmaf(fast_tanh(zf), 0.5f, 0.5f);
                const float gv = fast_tanh(zg);
                const float ov = fmaf(fast_tanh(zo), 0.5f, 0.5f);
                c[j] = fmaf(fv, c[j], iv * gv);
                h[j] = ov * fast_tanh(c[j]);
            }
        }
    }

    // Epilogue: hid = h @ fc_w^T + fc_b ; out = hid @ out_w^T + out_b ; sigmoid
    float acc = s_outb;
    #pragma unroll
    for (int k = 0; k < 15; k++) {
        float hv = s_fcb[k];
        #pragma unroll
        for (int j = 0; j < 5; j++) hv = fmaf(h[j], s_fcw[k * 5 + j], hv);
        acc = fmaf(hv, s_outw[k], acc);
    }
    out[seq] = 1.0f / (1.0f + __expf(-acc));
}

extern "C" void kernel_launch(void* const* d_in, const int* in_sizes, int n_in,
                              void* d_out, int out_size) {
    const float* x    = (const float*)d_in[0];
    const float* w_ih = (const float*)d_in[1];
    const float* w_hh = (const float*)d_in[2];
    const float* b_ih = (const float*)d_in[3];
    const float* b_hh = (const float*)d_in[4];
    const float* fc_w = (const float*)d_in[5];
    const float* fc_b = (const float*)d_in[6];
    const float* out_w = (const float*)d_in[7];
    const float* out_b = (const float*)d_in[8];
    float* out = (float*)d_out;

    lstm_kernel<<<256, 128>>>(x, w_ih, w_hh, b_ih, b_hh, fc_w, fc_b,
                              out_w, out_b, out);
}

// round 4
// speedup vs baseline: 1.7927x; 1.7927x over previous
#include <cuda_runtime.h>
#include <cuda_fp16.h>

__device__ __forceinline__ float fast_tanh(float x) {
    float y;
    asm("tanh.approx.f32 %0, %1;" : "=f"(y) : "f"(x));
    return y;
}

__device__ __forceinline__ __half2 tanh2(__half2 v) {
    unsigned a = *reinterpret_cast<unsigned*>(&v), b;
    asm("tanh.approx.f16x2 %0, %1;" : "=r"(b) : "r"(a));
    return *reinterpret_cast<__half2*>(&b);
}

// Gate rows in 4H=20: i=[0,5), f=[5,10), g=[10,15), o=[15,20)
// sigmoid(z)=0.5*tanh(z/2)+0.5, the 1/2 folded into i/f/o weight rows.
// fp16 packing: pair A_j=(i_j,f_j), pair B_j=(g_j,o_j).
// x-path (x*w_ih+b) in fp32 for precision, h-matmul in HFMA2, c/h in fp32.
__global__ __launch_bounds__(128) void lstm_kernel(
    const float* __restrict__ x,      // (32768, 600)
    const float* __restrict__ w_ih,   // (20, 1)
    const float* __restrict__ w_hh,   // (20, 5)
    const float* __restrict__ b_ih,   // (20,)
    const float* __restrict__ b_hh,   // (20,)
    const float* __restrict__ fc_w,   // (15, 5)
    const float* __restrict__ fc_b,   // (15,)
    const float* __restrict__ out_w,  // (1, 15)
    const float* __restrict__ out_b,  // (1,)
    float* __restrict__ out)          // (32768,)
{
    __shared__ float s_wih[20];       // folded
    __shared__ float s_b[20];         // folded
    __shared__ __half2 s_whhA[25];    // [j*5+k] = (whh[i_j,k]*.5, whh[f_j,k]*.5)
    __shared__ __half2 s_whhB[25];    // [j*5+k] = (whh[g_j,k],    whh[o_j,k]*.5)
    __shared__ float s_fcw[75];
    __shared__ float s_fcb[15];
    __shared__ float s_outw[15];
    __shared__ float s_outb;

    const int tid = threadIdx.x;
    if (tid < 20) {
        const float sc = (tid < 10 || tid >= 15) ? 0.5f : 1.0f;
        s_wih[tid] = w_ih[tid] * sc;
        s_b[tid]   = (b_ih[tid] + b_hh[tid]) * sc;
    }
    if (tid < 25) {
        const int j = tid / 5, k = tid % 5;
        s_whhA[tid] = __floats2half2_rn(w_hh[j * 5 + k] * 0.5f,
                                        w_hh[(5 + j) * 5 + k] * 0.5f);
        s_whhB[tid] = __floats2half2_rn(w_hh[(10 + j) * 5 + k],
                                        w_hh[(15 + j) * 5 + k] * 0.5f);
    }
    if (tid < 75) s_fcw[tid] = fc_w[tid];
    if (tid < 15) { s_fcb[tid] = fc_b[tid]; s_outw[tid] = out_w[tid]; }
    if (tid == 0) s_outb = out_b[0];
    __syncthreads();

    // Hoist weights into registers (loop-invariant).
    float wih[20], bb[20];
    __half2 whhA[25], whhB[25];
    #pragma unroll
    for (int r = 0; r < 20; r++) { wih[r] = s_wih[r]; bb[r] = s_b[r]; }
    #pragma unroll
    for (int m = 0; m < 25; m++) { whhA[m] = s_whhA[m]; whhB[m] = s_whhB[m]; }

    const __half2 hA_s = __floats2half2_rn(0.5f, 0.5f);
    const __half2 hA_b = __floats2half2_rn(0.5f, 0.5f);
    const __half2 hB_s = __floats2half2_rn(1.0f, 0.5f);
    const __half2 hB_b = __floats2half2_rn(0.0f, 0.5f);

    const int seq = blockIdx.x * 128 + tid;
    const float* xr = x + (long)seq * 600;

    float h[5] = {0.f, 0.f, 0.f, 0.f, 0.f};
    float c[5] = {0.f, 0.f, 0.f, 0.f, 0.f};

    #pragma unroll 1
    for (int t0 = 0; t0 < 600; t0 += 4) {
        const float4 xv = *reinterpret_cast<const float4*>(xr + t0);
        float xs[4] = {xv.x, xv.y, xv.z, xv.w};
        #pragma unroll
        for (int u = 0; u < 4; u++) {
            const float xt = xs[u];
            // h -> packed broadcast pairs
            __half2 hh[5];
            #pragma unroll
            for (int k = 0; k < 5; k++) hh[k] = __float2half2_rn(h[k]);

            __half2 zA[5], zB[5];
            #pragma unroll
            for (int j = 0; j < 5; j++) {
                // fp32 x-path, then pack
                zA[j] = __floats2half2_rn(fmaf(xt, wih[j],      bb[j]),
                                          fmaf(xt, wih[5 + j],  bb[5 + j]));
                zB[j] = __floats2half2_rn(fmaf(xt, wih[10 + j], bb[10 + j]),
                                          fmaf(xt, wih[15 + j], bb[15 + j]));
                #pragma unroll
                for (int k = 0; k < 5; k++) {
                    zA[j] = __hfma2(hh[k], whhA[j * 5 + k], zA[j]);
                    zB[j] = __hfma2(hh[k], whhB[j * 5 + k], zB[j]);
                }
            }
            #pragma unroll
            for (int j = 0; j < 5; j++) {
                const __half2 actA = __hfma2(tanh2(zA[j]), hA_s, hA_b); // (i, f)
                const __half2 actB = __hfma2(tanh2(zB[j]), hB_s, hB_b); // (g, o)
                const __half2 m = __hmul2(actA, actB);                   // (i*g, f*o)
                const float ig = __low2float(m);
                const float fv = __high2float(actA);
                const float ov = __high2float(actB);
                c[j] = fmaf(fv, c[j], ig);
                h[j] = ov * fast_tanh(c[j]);
            }
        }
    }

    // Epilogue (fp32, exact): hid = h @ fc_w^T + fc_b ; out = sigmoid(hid @ out_w^T + out_b)
    float acc = s_outb;
    #pragma unroll
    for (int k = 0; k < 15; k++) {
        float hv = s_fcb[k];
        #pragma unroll
        for (int j = 0; j < 5; j++) hv = fmaf(h[j], s_fcw[k * 5 + j], hv);
        acc = fmaf(hv, s_outw[k], acc);
    }
    out[seq] = 1.0f / (1.0f + __expf(-acc));
}

extern "C" void kernel_launch(void* const* d_in, const int* in_sizes, int n_in,
                              void* d_out, int out_size) {
    const float* x    = (const float*)d_in[0];
    const float* w_ih = (const float*)d_in[1];
    const float* w_hh = (const float*)d_in[2];
    const float* b_ih = (const float*)d_in[3];
    const float* b_hh = (const float*)d_in[4];
    const float* fc_w = (const float*)d_in[5];
    const float* fc_b = (const float*)d_in[6];
    const float* out_w = (const float*)d_in[7];
    const float* out_b = (const float*)d_in[8];
    float* out = (float*)d_out;

    lstm_kernel<<<256, 128>>>(x, w_ih, w_hh, b_ih, b_hh, fc_w, fc_b,
                              out_w, out_b, out);
}